// round 4
// baseline (speedup 1.0000x reference)
#include <cuda_runtime.h>
#include <cuda_fp16.h>

#define NB 8
#define NQ 100
#define MH 128
#define MW 128
#define OH 512
#define OW 512
#define NBLK 129                 // 4x4 output blocks per dim (shifted tiling)
#define QSTRIDE (MH*MW)

// Precomputed per-(b,q) duplicated half weights {w,w} and per-b constants K.
__device__ __half2 g_w0[NB*NQ];
__device__ __half2 g_w1[NB*NQ];
__device__ float2  g_K[NB];

__device__ __forceinline__ __half2 htanh2(__half2 x) {
    unsigned xi = *reinterpret_cast<unsigned*>(&x);
    unsigned yi;
    asm("tanh.approx.f16x2 %0, %1;" : "=r"(yi) : "r"(xi));
    return *reinterpret_cast<__half2*>(&yi);
}

// ---------------------------------------------------------------------------
// Kernel 1: softmax over 3 class logits, keep classes 0,1, pre-scale by 0.5,
// duplicate into half2, and block-reduce K_c[b] = 0.5 * sum_q w[b,q,c] (f32).
// ---------------------------------------------------------------------------
__global__ void weights_kernel(const float* __restrict__ cls) {
    int b = blockIdx.x;
    int q = threadIdx.x;          // 0..127
    __shared__ float s0[128], s1[128];
    float hw0 = 0.f, hw1 = 0.f;
    if (q < NQ) {
        const float* p = cls + (b*NQ + q)*3;
        float l0 = p[0], l1 = p[1], l2 = p[2];
        float m  = fmaxf(l0, fmaxf(l1, l2));
        float e0 = __expf(l0 - m), e1 = __expf(l1 - m), e2 = __expf(l2 - m);
        float inv = 0.5f / (e0 + e1 + e2);
        hw0 = e0 * inv; hw1 = e1 * inv;
        g_w0[b*NQ + q] = __half2half2(__float2half_rn(hw0));
        g_w1[b*NQ + q] = __half2half2(__float2half_rn(hw1));
    }
    s0[q] = hw0; s1[q] = hw1;
    __syncthreads();
    #pragma unroll
    for (int off = 64; off > 0; off >>= 1) {
        if (q < off) { s0[q] += s0[q + off]; s1[q] += s1[q + off]; }
        __syncthreads();
    }
    if (q == 0) g_K[b] = make_float2(s0[0], s1[0]);
}

// ---------------------------------------------------------------------------
// Kernel 2: one thread = one (b, r, s) -> 4x4 output block at rows 4r-2..4r+1,
// cols 4s-2..4s+1. Uses 2x2 input stencil (rows r-1,r / cols s-1,s, clamped).
// Entire lerp + tanh + weighted accumulation in packed fp16:
// out[b,c,y,x] = sum_q hw_c[q] * tanh(0.5 * bilerp(m_q)) + K_c[b]
// ---------------------------------------------------------------------------
__global__ void __launch_bounds__(256)
mask_kernel(const float* __restrict__ masks, float* __restrict__ out) {
    int idx = blockIdx.x * 256 + threadIdx.x;
    if (idx >= NB * NBLK * NBLK) return;

    int b   = idx / (NBLK * NBLK);
    int rem = idx - b * (NBLK * NBLK);
    int r   = rem / NBLK;
    int s   = rem - r * NBLK;

    int r0 = max(r - 1, 0), r1 = min(r, MH - 1);
    int c0 = max(s - 1, 0), c1 = min(s, MW - 1);
    int o00 = r0 * MW + c0, o01 = r0 * MW + c1;
    int o10 = r1 * MW + c0, o11 = r1 * MW + c1;

    const float*   p   = masks + (size_t)b * NQ * QSTRIDE;
    const __half2* wp0 = g_w0 + b * NQ;
    const __half2* wp1 = g_w1 + b * NQ;

    // fp16 accumulators: [row i][col-pair jj], per class
    __half2 hacc0[4][2], hacc1[4][2];
    #pragma unroll
    for (int i = 0; i < 4; i++)
        #pragma unroll
        for (int jj = 0; jj < 2; jj++) {
            hacc0[i][jj] = __half2half2(__ushort_as_half(0));
            hacc1[i][jj] = __half2half2(__ushort_as_half(0));
        }

    const __half2 H05 = __half2half2(__float2half_rn(0.5f));
    const __half2 FRH[4] = {
        __half2half2(__float2half_rn(0.125f)),
        __half2half2(__float2half_rn(0.375f)),
        __half2half2(__float2half_rn(0.625f)),
        __half2half2(__float2half_rn(0.875f))
    };

    #pragma unroll 2
    for (int q = 0; q < NQ; q++, p += QSTRIDE) {
        float a  = __ldg(p + o00);
        float bb = __ldg(p + o01);
        float c  = __ldg(p + o10);
        float d  = __ldg(p + o11);
        __half2 w0 = wp0[q];
        __half2 w1 = wp1[q];

        // pack {top-row, bot-row}: AC = {a, c}, BD = {b, d}, halved (sigmoid->tanh fold)
        __half2 AC = __hmul2(H05, __floats2half2_rn(a,  c));
        __half2 BD = __hmul2(H05, __floats2half2_rn(bb, d));
        __half2 E  = __hsub2(BD, AC);          // {et, eb}

        // horizontal lerp: TB[j] = {top[j], bot[j]}
        __half2 TB0 = __hfma2(FRH[0], E, AC);
        __half2 TB1 = __hfma2(FRH[1], E, AC);
        __half2 TB2 = __hfma2(FRH[2], E, AC);
        __half2 TB3 = __hfma2(FRH[3], E, AC);

        // repack over columns
        __half2 TOP01 = __lows2half2 (TB0, TB1);   // {top0, top1}
        __half2 TOP23 = __lows2half2 (TB2, TB3);
        __half2 BOT01 = __highs2half2(TB0, TB1);   // {bot0, bot1}
        __half2 BOT23 = __highs2half2(TB2, TB3);
        __half2 VD01  = __hsub2(BOT01, TOP01);
        __half2 VD23  = __hsub2(BOT23, TOP23);

        // vertical lerp + tanh + weighted accumulate
        #pragma unroll
        for (int i = 0; i < 4; i++) {
            __half2 V01 = __hfma2(FRH[i], VD01, TOP01);
            __half2 V23 = __hfma2(FRH[i], VD23, TOP23);
            __half2 T01 = htanh2(V01);
            __half2 T23 = htanh2(V23);
            hacc0[i][0] = __hfma2(w0, T01, hacc0[i][0]);
            hacc0[i][1] = __hfma2(w0, T23, hacc0[i][1]);
            hacc1[i][0] = __hfma2(w1, T01, hacc1[i][0]);
            hacc1[i][1] = __hfma2(w1, T23, hacc1[i][1]);
        }
    }

    // ---- store (predicated, float2 pairs, every output pixel written once) ----
    float2 K = g_K[b];
    int oyb = 4 * r - 2;
    int oxb = 4 * s - 2;
    bool xlo = (oxb >= 0);            // pair j=0,1
    bool xhi = (oxb + 3 < OW);        // pair j=2,3

    float* base0 = out + ((size_t)(b * 2 + 0) * OH) * OW;
    float* base1 = out + ((size_t)(b * 2 + 1) * OH) * OW;

    #pragma unroll
    for (int i = 0; i < 4; i++) {
        int oy = oyb + i;
        if ((unsigned)oy < (unsigned)OH) {
            float* r0p = base0 + (size_t)oy * OW + oxb;
            float* r1p = base1 + (size_t)oy * OW + oxb;
            if (xlo) {
                float2 f0 = __half22float2(hacc0[i][0]);
                float2 f1 = __half22float2(hacc1[i][0]);
                *(float2*)(r0p)     = make_float2(f0.x + K.x, f0.y + K.x);
                *(float2*)(r1p)     = make_float2(f1.x + K.y, f1.y + K.y);
            }
            if (xhi) {
                float2 f0 = __half22float2(hacc0[i][1]);
                float2 f1 = __half22float2(hacc1[i][1]);
                *(float2*)(r0p + 2) = make_float2(f0.x + K.x, f0.y + K.x);
                *(float2*)(r1p + 2) = make_float2(f1.x + K.y, f1.y + K.y);
            }
        }
    }
}

extern "C" void kernel_launch(void* const* d_in, const int* in_sizes, int n_in,
                              void* d_out, int out_size) {
    const float* cls   = (const float*)d_in[0];   // [8,100,3]
    const float* masks = (const float*)d_in[1];   // [8,100,128,128]
    float* out = (float*)d_out;                   // [8,2,512,512]

    weights_kernel<<<NB, 128>>>(cls);
    int total = NB * NBLK * NBLK;
    mask_kernel<<<(total + 255) / 256, 256>>>(masks, out);
}

// round 5
// speedup vs baseline: 1.1776x; 1.1776x over previous
#include <cuda_runtime.h>
#include <cuda_fp16.h>

#define NB 8
#define NQ 100
#define MH 128
#define MW 128
#define OH 512
#define OW 512
#define NBLK 129                 // 4x4 output blocks per dim (shifted tiling)
#define QSTRIDE (MH*MW)
#define NTOT (NB*NBLK*NBLK)

// Per-(b,q) packed duplicated half weights: .x = {w0,w0}, .y = {w1,w1} (as u32 bit patterns)
__device__ uint2  g_w[NB*NQ];
__device__ float2 g_K[NB];

__device__ __forceinline__ __half2 htanh2(__half2 x) {
    unsigned xi = *reinterpret_cast<unsigned*>(&x);
    unsigned yi;
    asm("tanh.approx.f16x2 %0, %1;" : "=r"(yi) : "r"(xi));
    return *reinterpret_cast<__half2*>(&yi);
}
__device__ __forceinline__ __half2 u2h2(unsigned u) {
    return *reinterpret_cast<__half2*>(&u);
}

// ---------------------------------------------------------------------------
// Kernel 1: softmax over 3 class logits, keep classes 0,1, pre-scale by 0.5,
// duplicate into half2 pairs, and block-reduce K_c[b] = 0.5*sum_q w (fp32).
// ---------------------------------------------------------------------------
__global__ void weights_kernel(const float* __restrict__ cls) {
    int b = blockIdx.x;
    int q = threadIdx.x;          // 0..127
    __shared__ float s0[128], s1[128];
    float hw0 = 0.f, hw1 = 0.f;
    if (q < NQ) {
        const float* p = cls + (b*NQ + q)*3;
        float l0 = p[0], l1 = p[1], l2 = p[2];
        float m  = fmaxf(l0, fmaxf(l1, l2));
        float e0 = __expf(l0 - m), e1 = __expf(l1 - m), e2 = __expf(l2 - m);
        float inv = 0.5f / (e0 + e1 + e2);
        hw0 = e0 * inv; hw1 = e1 * inv;
        __half2 h0 = __half2half2(__float2half_rn(hw0));
        __half2 h1 = __half2half2(__float2half_rn(hw1));
        g_w[b*NQ + q] = make_uint2(*reinterpret_cast<unsigned*>(&h0),
                                   *reinterpret_cast<unsigned*>(&h1));
    }
    s0[q] = hw0; s1[q] = hw1;
    __syncthreads();
    #pragma unroll
    for (int off = 64; off > 0; off >>= 1) {
        if (q < off) { s0[q] += s0[q + off]; s1[q] += s1[q + off]; }
        __syncthreads();
    }
    if (q == 0) g_K[b] = make_float2(s0[0], s1[0]);
}

// ---------------------------------------------------------------------------
// Kernel 2: one thread = one (b, r, s) -> 4x4 output block at rows 4r-2..4r+1,
// cols 4s-2..4s+1, from a 2x2 input stencil (rows r-1,r / cols s-1,s clamped).
// fp32 horizontal lerp -> single F2FP pack -> fp16 vertical lerp + tanh + acc.
// out[b,c,y,x] = sum_q hw_c[q] * tanh(0.5 * bilerp(m_q)) + K_c[b]
// ---------------------------------------------------------------------------
__global__ void __launch_bounds__(128, 8)
mask_kernel(const float* __restrict__ masks, float* __restrict__ out) {
    int idx = blockIdx.x * 128 + threadIdx.x;
    if (idx >= NTOT) return;

    int b   = idx / (NBLK * NBLK);
    int rem = idx - b * (NBLK * NBLK);
    int r   = rem / NBLK;
    int s   = rem - r * NBLK;

    int r0 = max(r - 1, 0), r1 = min(r, MH - 1);
    int c0 = max(s - 1, 0), c1 = min(s, MW - 1);
    int o00 = r0 * MW + c0, o01 = r0 * MW + c1;
    int o10 = r1 * MW + c0, o11 = r1 * MW + c1;

    const float* p  = masks + (size_t)b * NQ * QSTRIDE;
    const uint2* wp = g_w + b * NQ;

    // fp16 accumulators: [row i][col-pair jj], per class
    __half2 hacc0[4][2], hacc1[4][2];
    #pragma unroll
    for (int i = 0; i < 4; i++)
        #pragma unroll
        for (int jj = 0; jj < 2; jj++) {
            hacc0[i][jj] = __half2half2(__ushort_as_half(0));
            hacc1[i][jj] = __half2half2(__ushort_as_half(0));
        }

    const float fr[4] = {0.125f, 0.375f, 0.625f, 0.875f};
    const __half2 FRH[4] = {
        __half2half2(__float2half_rn(0.125f)),
        __half2half2(__float2half_rn(0.375f)),
        __half2half2(__float2half_rn(0.625f)),
        __half2half2(__float2half_rn(0.875f))
    };

    #pragma unroll 4
    for (int q = 0; q < NQ; q++, p += QSTRIDE) {
        float a  = __ldg(p + o00);
        float bb = __ldg(p + o01);
        float c  = __ldg(p + o10);
        float d  = __ldg(p + o11);
        uint2 wu = wp[q];
        __half2 w0 = u2h2(wu.x);
        __half2 w1 = u2h2(wu.y);

        // fold sigmoid->tanh 0.5 into halved corners (fp32)
        float ah = 0.5f * a;
        float et = fmaf(0.5f, bb, -ah);
        float ch = 0.5f * c;
        float eb = fmaf(0.5f, d, -ch);

        // horizontal lerp in fp32
        float top0 = fmaf(fr[0], et, ah), top1 = fmaf(fr[1], et, ah);
        float top2 = fmaf(fr[2], et, ah), top3 = fmaf(fr[3], et, ah);
        float bot0 = fmaf(fr[0], eb, ch), bot1 = fmaf(fr[1], eb, ch);
        float bot2 = fmaf(fr[2], eb, ch), bot3 = fmaf(fr[3], eb, ch);

        // single pack point: top pairs + vertical deltas as half2
        __half2 T01 = __floats2half2_rn(top0, top1);
        __half2 T23 = __floats2half2_rn(top2, top3);
        __half2 D01 = __floats2half2_rn(bot0 - top0, bot1 - top1);
        __half2 D23 = __floats2half2_rn(bot2 - top2, bot3 - top3);

        // vertical lerp + tanh + weighted accumulate (fp16)
        #pragma unroll
        for (int i = 0; i < 4; i++) {
            __half2 V01 = __hfma2(FRH[i], D01, T01);
            __half2 V23 = __hfma2(FRH[i], D23, T23);
            __half2 t01 = htanh2(V01);
            __half2 t23 = htanh2(V23);
            hacc0[i][0] = __hfma2(w0, t01, hacc0[i][0]);
            hacc0[i][1] = __hfma2(w0, t23, hacc0[i][1]);
            hacc1[i][0] = __hfma2(w1, t01, hacc1[i][0]);
            hacc1[i][1] = __hfma2(w1, t23, hacc1[i][1]);
        }
    }

    // ---- store (predicated, float2 pairs, every output pixel written once) ----
    float2 K = g_K[b];
    int oyb = 4 * r - 2;
    int oxb = 4 * s - 2;
    bool xlo = (oxb >= 0);            // pair j=0,1
    bool xhi = (oxb + 3 < OW);        // pair j=2,3

    float* base0 = out + ((size_t)(b * 2 + 0) * OH) * OW;
    float* base1 = out + ((size_t)(b * 2 + 1) * OH) * OW;

    #pragma unroll
    for (int i = 0; i < 4; i++) {
        int oy = oyb + i;
        if ((unsigned)oy < (unsigned)OH) {
            float* r0p = base0 + (size_t)oy * OW + oxb;
            float* r1p = base1 + (size_t)oy * OW + oxb;
            if (xlo) {
                float2 f0 = __half22float2(hacc0[i][0]);
                float2 f1 = __half22float2(hacc1[i][0]);
                *(float2*)(r0p)     = make_float2(f0.x + K.x, f0.y + K.x);
                *(float2*)(r1p)     = make_float2(f1.x + K.y, f1.y + K.y);
            }
            if (xhi) {
                float2 f0 = __half22float2(hacc0[i][1]);
                float2 f1 = __half22float2(hacc1[i][1]);
                *(float2*)(r0p + 2) = make_float2(f0.x + K.x, f0.y + K.x);
                *(float2*)(r1p + 2) = make_float2(f1.x + K.y, f1.y + K.y);
            }
        }
    }
}

extern "C" void kernel_launch(void* const* d_in, const int* in_sizes, int n_in,
                              void* d_out, int out_size) {
    const float* cls   = (const float*)d_in[0];   // [8,100,3]
    const float* masks = (const float*)d_in[1];   // [8,100,128,128]
    float* out = (float*)d_out;                   // [8,2,512,512]

    weights_kernel<<<NB, 128>>>(cls);
    int total = NTOT;
    mask_kernel<<<(total + 127) / 128, 128>>>(masks, out);
}